// round 14
// baseline (speedup 1.0000x reference)
#include <cuda_runtime.h>

#define BATCH 32
#define CH    512
#define HH    64
#define WW    64
#define KSEL  256           // RATIO 0.5 * 512
#define PLANE (HH * WW)     // 4096
#define CHUNKB 8            // batches per serial chunk: 67MB reads < 126MB L2
#define NCHUNK (BATCH / CHUNKB)

// Scratch (allocation-free rule: __device__ globals)
__device__ double g_scores2[BATCH * CH * 2];   // per-half-plane fp64 partials
__device__ int    g_idx[BATCH * KSEL];

// ---------------------------------------------------------------------------
// Kernel 1: curvature score, ONE WARP PER HALF-PLANE (R14).
// Half 0: output rows 0..30 (reads rows 0..32); half 1: outputs 31..61
// (reads 31..63). 2x block parallelism vs warp-per-plane -> chunked grids
// stay near a full wave (R13's 512-block chunks ran at occ 20%).
//  - lane l loads float2 at cols (2l,2l+1) per row (LDG.64)
//  - 8-deep register prefetch queue q[i&7] (consume row r0+i+2, load r0+i+10)
//  - symmetric-stencil factorization: conv = wc*(tA+tC)+we*(mA+mC+tB)+w4*mB
//  - branchless; lane 31's Kahan state zeroed pre-reduce
//  - loop split: prefetch i<23 (last load i=22 -> row r0+32), drain i=23..30
//  - NUMERICS: fp32 Kahan in-loop + fp64 warp reduce; half-partials stored as
//    DOUBLE, summed exactly in topk -> error identical to the passing config.
// ---------------------------------------------------------------------------
__global__ __launch_bounds__(128, 10) void score_kernel(const float* __restrict__ x,
                                                         const float* __restrict__ wgt,
                                                         int h0) {
    const int lane = threadIdx.x & 31;
    const int warp = threadIdx.x >> 5;
    const int h     = h0 + blockIdx.x * 4 + warp;   // half-plane index
    const int plane = h >> 1;
    const int r0    = (h & 1) * 31;                 // first output row

    const float wc = __ldg(wgt + 0);   // corners (-1/16)
    const float we = __ldg(wgt + 1);   // edges   ( 5/16)
    const float w4 = __ldg(wgt + 4);   // center  (-1)

    // float2 view of this half-plane: row j at b2[j*32]
    const float2* b2 = reinterpret_cast<const float2*>(x)
                       + (size_t)plane * (PLANE / 2) + (size_t)r0 * 32 + lane;
    const unsigned FULL = 0xffffffffu;

    // prologue: rows r0, r0+1 -> factored state; rows r0+2..r0+9 -> queue
    const float2 ra = b2[0 * 32];
    const float2 rb = b2[1 * 32];
    float2 q[8];
    #pragma unroll
    for (int j = 0; j < 8; ++j) q[j] = b2[(j + 2) * 32];

    const float ranx = __shfl_down_sync(FULL, ra.x, 1);
    const float rany = __shfl_down_sync(FULL, ra.y, 1);
    const float rbnx = __shfl_down_sync(FULL, rb.x, 1);
    const float rbny = __shfl_down_sync(FULL, rb.y, 1);

    float tA0 = ra.x + ranx, tA1 = ra.y + rany;
    float mA0 = ra.y,        mA1 = ranx;
    float tB0 = rb.x + rbnx, tB1 = rb.y + rbny;
    float mB0 = rb.y,        mB1 = rbnx;

    float sum  = 0.0f;   // Kahan accumulator
    float comp = 0.0f;   // Kahan compensation

    auto body = [&](const float2 c) {
        const float cnx = __shfl_down_sync(FULL, c.x, 1);
        const float cny = __shfl_down_sync(FULL, c.y, 1);
        const float tC0 = c.x + cnx, tC1 = c.y + cny;
        const float mC0 = c.y,       mC1 = cnx;

        const float u0 = tA0 + tC0;
        float v0 = mA0 + mC0;
        v0 += tB0;
        float conv0 = wc * u0;
        conv0 = fmaf(we, v0, conv0);
        conv0 = fmaf(w4, mB0, conv0);

        const float u1 = tA1 + tC1;
        float v1 = mA1 + mC1;
        v1 += tB1;
        float conv1 = wc * u1;
        conv1 = fmaf(we, v1, conv1);
        conv1 = fmaf(w4, mB1, conv1);

        const float rowsum = fabsf(conv0) + fabsf(conv1);
        const float y = __fadd_rn(rowsum, -comp);
        const float t = __fadd_rn(sum, y);
        comp = __fadd_rn(__fadd_rn(t, -sum), -y);
        sum = t;

        tA0 = tB0; tA1 = tB1; mA0 = mB0; mA1 = mB1;
        tB0 = tC0; tB1 = tC1; mB0 = mC0; mB1 = mC1;
    };

    // 31 outputs: prefetch rows r0+10..r0+32 (i+10 <= 32 for i < 23)
    #pragma unroll 8
    for (int i = 0; i < 23; ++i) {
        const float2 c = q[i & 7];
        q[i & 7] = b2[(i + 10) * 32];
        body(c);
    }
    // drain: consume rows r0+25..r0+32 (stored at i=15..22)
    #pragma unroll
    for (int i = 23; i < 31; ++i) {
        body(q[i & 7]);
    }

    // lane 31 (cols 62/63) only fed shuffles — drop its contribution
    if (lane == 31) { sum = 0.0f; comp = 0.0f; }

    // fp64 warp shuffle-tree reduction; store half-partial as double
    double acc = (double)sum - (double)comp;
    #pragma unroll
    for (int off = 16; off > 0; off >>= 1)
        acc += __shfl_xor_sync(FULL, acc, off);
    if (lane == 0) g_scores2[h] = acc;
}

// ---------------------------------------------------------------------------
// Kernel 2: per-batch top-k (k=256) via exact rank counting (lax.top_k order:
// descending value, ties -> lower index). Sums the two half-plane fp64
// partials exactly; ranks compared in fp64.
// ---------------------------------------------------------------------------
__global__ __launch_bounds__(512) void topk_kernel(int b0) {
    __shared__ double s[CH];
    const int b   = b0 + blockIdx.x;
    const int tid = threadIdx.x;

    const int i = b * CH + tid;
    s[tid] = g_scores2[2 * i] + g_scores2[2 * i + 1];
    __syncthreads();

    const double my = s[tid];
    int rank = 0;
    #pragma unroll 8
    for (int j = 0; j < CH; ++j) {
        const double v = s[j];
        rank += (v > my) || (v == my && j < tid);
    }
    if (rank < KSEL) g_idx[b * KSEL + rank] = tid;
}

// ---------------------------------------------------------------------------
// Kernel 3: gather selected channel planes. 128 thr x 8 independent float4
// copies. Reads DEFAULT-cached: score(chunk) streamed these 67MB through L2
// immediately before, so reads should be L2 hits. Writes streaming (__stcs).
// ---------------------------------------------------------------------------
__global__ __launch_bounds__(128) void gather_kernel(const float* __restrict__ x,
                                                     float* __restrict__ out,
                                                     int b0) {
    const int b = b0 + blockIdx.y;
    const int r = blockIdx.x;
    const int c = __ldg(&g_idx[b * KSEL + r]);   // broadcast

    const float4* __restrict__ src = reinterpret_cast<const float4*>(x)
                        + ((size_t)(b * CH + c)) * (PLANE / 4);
    float4* __restrict__ dst = reinterpret_cast<float4*>(out)
                  + ((size_t)(b * KSEL + r)) * (PLANE / 4);
    const int tid = threadIdx.x;

    float4 v0 = src[tid + 0 * 128];
    float4 v1 = src[tid + 1 * 128];
    float4 v2 = src[tid + 2 * 128];
    float4 v3 = src[tid + 3 * 128];
    float4 v4 = src[tid + 4 * 128];
    float4 v5 = src[tid + 5 * 128];
    float4 v6 = src[tid + 6 * 128];
    float4 v7 = src[tid + 7 * 128];
    __stcs(&dst[tid + 0 * 128], v0);
    __stcs(&dst[tid + 1 * 128], v1);
    __stcs(&dst[tid + 2 * 128], v2);
    __stcs(&dst[tid + 3 * 128], v3);
    __stcs(&dst[tid + 4 * 128], v4);
    __stcs(&dst[tid + 5 * 128], v5);
    __stcs(&dst[tid + 6 * 128], v6);
    __stcs(&dst[tid + 7 * 128], v7);
}

// ---------------------------------------------------------------------------
// R14: SERIAL chunked pipeline, single stream (R12/R13 showed stream forks
// are unreliable here). Chunk = 8 batches: score streams 67MB through L2,
// topk (0.4us), then gather re-reads 33.5MB of it while L2-resident.
// Half-plane score keeps chunk grids at 2048 blocks (~1.4 waves).
// ---------------------------------------------------------------------------
extern "C" void kernel_launch(void* const* d_in, const int* in_sizes, int n_in,
                              void* d_out, int out_size) {
    const float* x = (const float*)d_in[0];
    const float* w = (const float*)d_in[1];
    if (n_in >= 2 && in_sizes[0] == 9) {   // defensive input-order check
        const float* t = x; x = w; w = t;
    }
    float* out = (float*)d_out;

    const int halvesPerChunk = CHUNKB * CH * 2;      // 8192 half-planes
    const int scoreBlocks    = halvesPerChunk / 4;   // 2048

    for (int c = 0; c < NCHUNK; ++c) {
        const int b0 = c * CHUNKB;
        score_kernel<<<scoreBlocks, 128>>>(x, w, b0 * CH * 2);
        topk_kernel<<<CHUNKB, 512>>>(b0);
        gather_kernel<<<dim3(KSEL, CHUNKB), 128>>>(x, out, b0);
    }
}

// round 15
// speedup vs baseline: 7.8300x; 7.8300x over previous
#include <cuda_runtime.h>

#define BATCH 32
#define CH    512
#define HH    64
#define WW    64
#define KSEL  256           // RATIO 0.5 * 512
#define PLANE (HH * WW)     // 4096

// Scratch (allocation-free rule: __device__ globals)
__device__ float g_scores[BATCH * CH];
__device__ int   g_idx[BATCH * KSEL];

// ---------------------------------------------------------------------------
// Kernel 1: per-(b,c) plane curvature score = sum |valid 3x3 xcorr response|
// ONE WARP per plane, straight from global (no smem). R11 config (best known:
// 44.9us, DRAM 77%).
//  - lane l loads float2 at cols (2l,2l+1) per row (LDG.64, each byte once)
//  - 8-deep register prefetch queue q[i&7] (consume row i+2, load row i+10)
//  - symmetric-stencil factorization: conv = wc*(tA+tC)+we*(mA+mC+tB)+w4*mB
//  - branchless; lane 31's Kahan state zeroed pre-reduce
//  - loop split: prefetch i<54 (last load i=53 -> row 63), drain i=54..61
//  - NUMERICS: fp32 Kahan in-loop + fp64 final warp reduce ONLY (R14 lesson:
//    fp64 in any hot loop is ~1 op/cyc/SM on sm_103a — never again).
// ---------------------------------------------------------------------------
__global__ __launch_bounds__(128, 10) void score_kernel(const float* __restrict__ x,
                                                         const float* __restrict__ wgt) {
    const int lane  = threadIdx.x & 31;
    const int warp  = threadIdx.x >> 5;
    const int plane = blockIdx.x * 4 + warp;

    const float wc = __ldg(wgt + 0);   // corners (-1/16)
    const float we = __ldg(wgt + 1);   // edges   ( 5/16)
    const float w4 = __ldg(wgt + 4);   // center  (-1)

    const float2* b2 = reinterpret_cast<const float2*>(x)
                       + (size_t)plane * (PLANE / 2) + lane;
    const unsigned FULL = 0xffffffffu;

    // prologue: rows 0,1 -> factored state; rows 2..9 -> prefetch queue
    const float2 r0 = b2[0 * 32];
    const float2 r1 = b2[1 * 32];
    float2 q[8];
    #pragma unroll
    for (int j = 0; j < 8; ++j) q[j] = b2[(j + 2) * 32];

    const float r0nx = __shfl_down_sync(FULL, r0.x, 1);
    const float r0ny = __shfl_down_sync(FULL, r0.y, 1);
    const float r1nx = __shfl_down_sync(FULL, r1.x, 1);
    const float r1ny = __shfl_down_sync(FULL, r1.y, 1);

    float tA0 = r0.x + r0nx, tA1 = r0.y + r0ny;
    float mA0 = r0.y,        mA1 = r0nx;
    float tB0 = r1.x + r1nx, tB1 = r1.y + r1ny;
    float mB0 = r1.y,        mB1 = r1nx;

    float sum  = 0.0f;   // Kahan accumulator
    float comp = 0.0f;   // Kahan compensation

    auto body = [&](const float2 c) {
        const float cnx = __shfl_down_sync(FULL, c.x, 1);
        const float cny = __shfl_down_sync(FULL, c.y, 1);
        const float tC0 = c.x + cnx, tC1 = c.y + cny;
        const float mC0 = c.y,       mC1 = cnx;

        const float u0 = tA0 + tC0;
        float v0 = mA0 + mC0;
        v0 += tB0;
        float conv0 = wc * u0;
        conv0 = fmaf(we, v0, conv0);
        conv0 = fmaf(w4, mB0, conv0);

        const float u1 = tA1 + tC1;
        float v1 = mA1 + mC1;
        v1 += tB1;
        float conv1 = wc * u1;
        conv1 = fmaf(we, v1, conv1);
        conv1 = fmaf(w4, mB1, conv1);

        const float rowsum = fabsf(conv0) + fabsf(conv1);
        const float y = __fadd_rn(rowsum, -comp);
        const float t = __fadd_rn(sum, y);
        comp = __fadd_rn(__fadd_rn(t, -sum), -y);
        sum = t;

        tA0 = tB0; tA1 = tB1; mA0 = mB0; mA1 = mB1;
        tB0 = tC0; tB1 = tC1; mB0 = mC0; mB1 = mC1;
    };

    #pragma unroll 8
    for (int i = 0; i < 54; ++i) {
        const float2 c = q[i & 7];
        q[i & 7] = b2[(i + 10) * 32];
        body(c);
    }
    #pragma unroll
    for (int i = 54; i < HH - 2; ++i) {
        body(q[i & 7]);
    }

    if (lane == 31) { sum = 0.0f; comp = 0.0f; }

    double acc = (double)sum - (double)comp;
    #pragma unroll
    for (int off = 16; off > 0; off >>= 1)
        acc += __shfl_xor_sync(FULL, acc, off);
    if (lane == 0) g_scores[plane] = (float)acc;
}

// ---------------------------------------------------------------------------
// Kernel 2: per-batch top-k (k=256) via exact rank counting in FP32
// (lax.top_k order: descending value, ties -> lower index).
// ---------------------------------------------------------------------------
__global__ __launch_bounds__(512) void topk_kernel() {
    __shared__ float s[CH];
    const int b   = blockIdx.x;
    const int tid = threadIdx.x;

    s[tid] = g_scores[b * CH + tid];
    __syncthreads();

    const float my = s[tid];
    int rank = 0;
    #pragma unroll 8
    for (int j = 0; j < CH; ++j) {
        const float v = s[j];
        rank += (v > my) || (v == my && j < tid);
    }
    if (rank < KSEL) g_idx[b * KSEL + rank] = tid;
}

// ---------------------------------------------------------------------------
// Kernel 3: gather selected channel planes. 128 thr x 8 independent float4
// copies. R15: REVERSED batch traversal — score streamed batches 0..31, so
// L2 (126MB) holds the tail (~batches 17..31) when gather starts; consuming
// the tail first (blocks launch in bid order) converts those reads to L2
// hits before gather's own traffic evicts them. Reads default-cached on
// purpose; writes streaming (__stcs, zero reuse).
// ---------------------------------------------------------------------------
__global__ __launch_bounds__(128) void gather_kernel(const float* __restrict__ x,
                                                     float* __restrict__ out) {
    const int b = (BATCH - 1) - blockIdx.y;      // reverse order
    const int r = blockIdx.x;
    const int c = __ldg(&g_idx[b * KSEL + r]);   // broadcast

    const float4* __restrict__ src = reinterpret_cast<const float4*>(x)
                        + ((size_t)(b * CH + c)) * (PLANE / 4);
    float4* __restrict__ dst = reinterpret_cast<float4*>(out)
                  + ((size_t)(b * KSEL + r)) * (PLANE / 4);
    const int tid = threadIdx.x;

    float4 v0 = src[tid + 0 * 128];
    float4 v1 = src[tid + 1 * 128];
    float4 v2 = src[tid + 2 * 128];
    float4 v3 = src[tid + 3 * 128];
    float4 v4 = src[tid + 4 * 128];
    float4 v5 = src[tid + 5 * 128];
    float4 v6 = src[tid + 6 * 128];
    float4 v7 = src[tid + 7 * 128];
    __stcs(&dst[tid + 0 * 128], v0);
    __stcs(&dst[tid + 1 * 128], v1);
    __stcs(&dst[tid + 2 * 128], v2);
    __stcs(&dst[tid + 3 * 128], v3);
    __stcs(&dst[tid + 4 * 128], v4);
    __stcs(&dst[tid + 5 * 128], v5);
    __stcs(&dst[tid + 6 * 128], v6);
    __stcs(&dst[tid + 7 * 128], v7);
}

// ---------------------------------------------------------------------------
// R15: single stream, 3 launches (R12-R14 showed forks/chunking net-lose).
// ---------------------------------------------------------------------------
extern "C" void kernel_launch(void* const* d_in, const int* in_sizes, int n_in,
                              void* d_out, int out_size) {
    const float* x = (const float*)d_in[0];
    const float* w = (const float*)d_in[1];
    if (n_in >= 2 && in_sizes[0] == 9) {   // defensive input-order check
        const float* t = x; x = w; w = t;
    }
    float* out = (float*)d_out;

    score_kernel<<<(BATCH * CH) / 4, 128>>>(x, w);
    topk_kernel<<<BATCH, 512>>>();
    gather_kernel<<<dim3(KSEL, BATCH), 128>>>(x, out);
}